// round 1
// baseline (speedup 1.0000x reference)
#include <cuda_runtime.h>
#include <math.h>

#define B_DIM 2
#define S_DIM 8192
#define E_DIM 128

// Scratch: Q and K stored TRANSPOSED [b][e][s] so attention tile loads are
// coalesced and SMEM-conflict-free with no in-kernel transpose. V natural [b][s][e].
__device__ float g_Qt[B_DIM * E_DIM * S_DIM];
__device__ float g_Kt[B_DIM * E_DIM * S_DIM];
__device__ float g_V [B_DIM * S_DIM * E_DIM];

// ---------------------------------------------------------------------------
// Projection: out[o][s] = sum_e W[o][e] * x[s][e] + b[o]
// grid = ((B*S)/128, 3). which: 0->Q (transposed out), 1->K (transposed), 2->V (natural)
// Block: 128 rows (s) x 128 outputs (o). 256 threads, 8x8 register tile.
// ---------------------------------------------------------------------------
__global__ __launch_bounds__(256) void proj_kernel(
    const float* __restrict__ x,
    const float* __restrict__ Wq, const float* __restrict__ bq,
    const float* __restrict__ Wk, const float* __restrict__ bk,
    const float* __restrict__ Wv, const float* __restrict__ bvp)
{
    extern __shared__ float sm[];
    float* xs = sm;              // [e][s] 128x128 (transposed in)
    float* ws = sm + 128 * 128;  // [e][o] 128x128 (transposed in)

    const int t = threadIdx.x;
    const int which = blockIdx.y;
    const float* __restrict__ W  = (which == 0) ? Wq : (which == 1) ? Wk : Wv;
    const float* __restrict__ bb = (which == 0) ? bq : (which == 1) ? bk : bvp;

    const int row_base = blockIdx.x * 128;   // global row in [0, B*S)

    // 4x4 micro-tile transpose loads: lanes 0..7 vary row-group -> conflict-free STS.128
    const int rm = t & 7;
    const int cm = t >> 3;      // 0..31
    const int c0 = 4 * cm;
    #pragma unroll
    for (int p = 0; p < 4; ++p) {
        const int r0 = 32 * p + 4 * rm;
        float4 v0 = *(const float4*)&x[(row_base + r0 + 0) * E_DIM + c0];
        float4 v1 = *(const float4*)&x[(row_base + r0 + 1) * E_DIM + c0];
        float4 v2 = *(const float4*)&x[(row_base + r0 + 2) * E_DIM + c0];
        float4 v3 = *(const float4*)&x[(row_base + r0 + 3) * E_DIM + c0];
        *(float4*)&xs[(c0 + 0) * 128 + r0] = make_float4(v0.x, v1.x, v2.x, v3.x);
        *(float4*)&xs[(c0 + 1) * 128 + r0] = make_float4(v0.y, v1.y, v2.y, v3.y);
        *(float4*)&xs[(c0 + 2) * 128 + r0] = make_float4(v0.z, v1.z, v2.z, v3.z);
        *(float4*)&xs[(c0 + 3) * 128 + r0] = make_float4(v0.w, v1.w, v2.w, v3.w);

        float4 u0 = *(const float4*)&W[(r0 + 0) * E_DIM + c0];
        float4 u1 = *(const float4*)&W[(r0 + 1) * E_DIM + c0];
        float4 u2 = *(const float4*)&W[(r0 + 2) * E_DIM + c0];
        float4 u3 = *(const float4*)&W[(r0 + 3) * E_DIM + c0];
        *(float4*)&ws[(c0 + 0) * 128 + r0] = make_float4(u0.x, u1.x, u2.x, u3.x);
        *(float4*)&ws[(c0 + 1) * 128 + r0] = make_float4(u0.y, u1.y, u2.y, u3.y);
        *(float4*)&ws[(c0 + 2) * 128 + r0] = make_float4(u0.z, u1.z, u2.z, u3.z);
        *(float4*)&ws[(c0 + 3) * 128 + r0] = make_float4(u0.w, u1.w, u2.w, u3.w);
    }
    __syncthreads();

    const int og = t >> 4;       // 0..15
    const int sg = t & 15;       // 0..15
    const int o0 = 8 * og;
    const int sA = 4 * sg;       // split columns {4sg, 64+4sg} -> conflict-free LDS
    const int sB = 64 + 4 * sg;

    float acc[8][8];
    #pragma unroll
    for (int r = 0; r < 8; ++r)
        #pragma unroll
        for (int c = 0; c < 8; ++c) acc[r][c] = 0.0f;

    #pragma unroll 8
    for (int e = 0; e < 128; ++e) {
        float4 a0 = *(const float4*)&ws[e * 128 + o0];
        float4 a1 = *(const float4*)&ws[e * 128 + o0 + 4];
        float4 b0 = *(const float4*)&xs[e * 128 + sA];
        float4 b1 = *(const float4*)&xs[e * 128 + sB];
        float av[8] = {a0.x, a0.y, a0.z, a0.w, a1.x, a1.y, a1.z, a1.w};
        float bw[8] = {b0.x, b0.y, b0.z, b0.w, b1.x, b1.y, b1.z, b1.w};
        #pragma unroll
        for (int r = 0; r < 8; ++r)
            #pragma unroll
            for (int c = 0; c < 8; ++c)
                acc[r][c] += av[r] * bw[c];
    }

    float brow[8];
    #pragma unroll
    for (int r = 0; r < 8; ++r) brow[r] = __ldg(&bb[o0 + r]);
    #pragma unroll
    for (int r = 0; r < 8; ++r)
        #pragma unroll
        for (int c = 0; c < 8; ++c) acc[r][c] += brow[r];

    if (which < 2) {
        float* __restrict__ dst = (which == 0) ? g_Qt : g_Kt;
        const int b    = row_base / S_DIM;
        const int s_in = row_base % S_DIM;
        #pragma unroll
        for (int r = 0; r < 8; ++r) {
            *(float4*)&dst[(b * E_DIM + o0 + r) * S_DIM + s_in + sA] =
                make_float4(acc[r][0], acc[r][1], acc[r][2], acc[r][3]);
            *(float4*)&dst[(b * E_DIM + o0 + r) * S_DIM + s_in + sB] =
                make_float4(acc[r][4], acc[r][5], acc[r][6], acc[r][7]);
        }
    } else {
        #pragma unroll
        for (int c = 0; c < 8; ++c) {
            const int scol = (c < 4) ? (sA + c) : (sB + c - 4);
            const int row  = row_base + scol;
            *(float4*)&g_V[row * E_DIM + o0] =
                make_float4(acc[0][c], acc[1][c], acc[2][c], acc[3][c]);
            *(float4*)&g_V[row * E_DIM + o0 + 4] =
                make_float4(acc[4][c], acc[5][c], acc[6][c], acc[7][c]);
        }
    }
}

// ---------------------------------------------------------------------------
// Flash attention, fp32. grid = (S/64, B). Block tile: 64 q x 128 kv per iter.
// 256 threads: ti = t>>4 (4 query rows), tj = t&15 (8 kv cols split {4tj, 64+4tj}).
// ---------------------------------------------------------------------------
__global__ __launch_bounds__(256) void attn_kernel(float* __restrict__ out)
{
    extern __shared__ float sm[];
    float* Qs = sm;                      // [e][i] 128x64
    float* Ks = Qs + 128 * 64;           // [e][j] 128x128
    float* Vs = Ks + 128 * 128;          // [j][e] 128x128
    float* Ps = Vs + 128 * 128;          // [i][j] 64x128

    const int t  = threadIdx.x;
    const int b  = blockIdx.y;
    const int q0 = blockIdx.x * 64;

    // Load Q tile (pre-transposed in global): coalesced, conflict-free
    {
        int f4 = t;
        #pragma unroll
        for (int p = 0; p < 8; ++p, f4 += 256) {
            int e = f4 >> 4;
            int c = (f4 & 15) * 4;
            *(float4*)&Qs[e * 64 + c] =
                *(const float4*)&g_Qt[(b * E_DIM + e) * S_DIM + q0 + c];
        }
    }

    const int ti = t >> 4;
    const int tj = t & 15;
    const int i0 = 4 * ti;
    const int jA = 4 * tj;
    const int jB = 64 + 4 * tj;

    float oacc[4][8];
    #pragma unroll
    for (int r = 0; r < 4; ++r)
        #pragma unroll
        for (int c = 0; c < 8; ++c) oacc[r][c] = 0.0f;
    float mrow[4] = {-1e30f, -1e30f, -1e30f, -1e30f};
    float lrow[4] = {0.0f, 0.0f, 0.0f, 0.0f};

    // scores scaled by 1/sqrt(E) and converted to log2 domain in one multiply
    const float kscale = 0.08838834764831845f * 1.4426950408889634f;

    for (int kt = 0; kt < S_DIM / 128; ++kt) {
        const int k0 = kt * 128;
        {
            int f4 = t;
            #pragma unroll
            for (int p = 0; p < 16; ++p, f4 += 256) {
                int r = f4 >> 5;
                int c = (f4 & 31) * 4;
                *(float4*)&Ks[r * 128 + c] =
                    *(const float4*)&g_Kt[(b * E_DIM + r) * S_DIM + k0 + c];
                *(float4*)&Vs[r * 128 + c] =
                    *(const float4*)&g_V[(b * S_DIM + k0 + r) * E_DIM + c];
            }
        }
        __syncthreads();

        // ---- scores: S = Q K^T  (4x8 frag per thread) ----
        float sc[4][8];
        #pragma unroll
        for (int r = 0; r < 4; ++r)
            #pragma unroll
            for (int c = 0; c < 8; ++c) sc[r][c] = 0.0f;

        #pragma unroll 8
        for (int e = 0; e < 128; ++e) {
            float4 q  = *(const float4*)&Qs[e * 64 + i0];
            float4 ka = *(const float4*)&Ks[e * 128 + jA];
            float4 kb = *(const float4*)&Ks[e * 128 + jB];
            float qv[4] = {q.x, q.y, q.z, q.w};
            float kv[8] = {ka.x, ka.y, ka.z, ka.w, kb.x, kb.y, kb.z, kb.w};
            #pragma unroll
            for (int r = 0; r < 4; ++r)
                #pragma unroll
                for (int c = 0; c < 8; ++c)
                    sc[r][c] += qv[r] * kv[c];
        }

        // ---- online softmax (log2 domain) ----
        #pragma unroll
        for (int r = 0; r < 4; ++r) {
            #pragma unroll
            for (int c = 0; c < 8; ++c) sc[r][c] *= kscale;
            float rmax = sc[r][0];
            #pragma unroll
            for (int c = 1; c < 8; ++c) rmax = fmaxf(rmax, sc[r][c]);
            #pragma unroll
            for (int off = 8; off > 0; off >>= 1)
                rmax = fmaxf(rmax, __shfl_xor_sync(0xffffffffu, rmax, off));

            const float mnew  = fmaxf(mrow[r], rmax);
            const float alpha = exp2f(mrow[r] - mnew);
            mrow[r] = mnew;

            float rsum = 0.0f;
            #pragma unroll
            for (int c = 0; c < 8; ++c) {
                sc[r][c] = exp2f(sc[r][c] - mnew);
                rsum += sc[r][c];
            }
            #pragma unroll
            for (int off = 8; off > 0; off >>= 1)
                rsum += __shfl_xor_sync(0xffffffffu, rsum, off);

            lrow[r] = lrow[r] * alpha + rsum;
            #pragma unroll
            for (int c = 0; c < 8; ++c) oacc[r][c] *= alpha;
        }

        // ---- write P tile ----
        #pragma unroll
        for (int r = 0; r < 4; ++r) {
            *(float4*)&Ps[(i0 + r) * 128 + jA] =
                make_float4(sc[r][0], sc[r][1], sc[r][2], sc[r][3]);
            *(float4*)&Ps[(i0 + r) * 128 + jB] =
                make_float4(sc[r][4], sc[r][5], sc[r][6], sc[r][7]);
        }
        __syncthreads();

        // ---- O += P V  (thread output cols = {jA..jA+3, jB..jB+3}) ----
        #pragma unroll 4
        for (int j = 0; j < 128; ++j) {
            float4 va = *(const float4*)&Vs[j * 128 + jA];
            float4 vb = *(const float4*)&Vs[j * 128 + jB];
            float pv[4];
            #pragma unroll
            for (int r = 0; r < 4; ++r) pv[r] = Ps[(i0 + r) * 128 + j];
            float vv[8] = {va.x, va.y, va.z, va.w, vb.x, vb.y, vb.z, vb.w};
            #pragma unroll
            for (int r = 0; r < 4; ++r)
                #pragma unroll
                for (int c = 0; c < 8; ++c)
                    oacc[r][c] += pv[r] * vv[c];
        }
        __syncthreads();
    }

    // ---- epilogue: normalize and store ----
    #pragma unroll
    for (int r = 0; r < 4; ++r) {
        const float inv = 1.0f / lrow[r];
        const int row = (b * S_DIM + q0 + i0 + r) * E_DIM;
        *(float4*)&out[row + jA] = make_float4(oacc[r][0] * inv, oacc[r][1] * inv,
                                               oacc[r][2] * inv, oacc[r][3] * inv);
        *(float4*)&out[row + jB] = make_float4(oacc[r][4] * inv, oacc[r][5] * inv,
                                               oacc[r][6] * inv, oacc[r][7] * inv);
    }
}

extern "C" void kernel_launch(void* const* d_in, const int* in_sizes, int n_in,
                              void* d_out, int out_size)
{
    (void)in_sizes; (void)n_in; (void)out_size;
    const float* x  = (const float*)d_in[0];
    const float* Wq = (const float*)d_in[1];
    const float* bq = (const float*)d_in[2];
    const float* Wk = (const float*)d_in[3];
    const float* bk = (const float*)d_in[4];
    const float* Wv = (const float*)d_in[5];
    const float* bv = (const float*)d_in[6];
    float* out = (float*)d_out;

    cudaFuncSetAttribute(proj_kernel, cudaFuncAttributeMaxDynamicSharedMemorySize, 131072);
    cudaFuncSetAttribute(attn_kernel, cudaFuncAttributeMaxDynamicSharedMemorySize, 196608);

    dim3 pg((B_DIM * S_DIM) / 128, 3);
    proj_kernel<<<pg, 256, 131072>>>(x, Wq, bq, Wk, bk, Wv, bv);

    dim3 ag(S_DIM / 64, B_DIM);
    attn_kernel<<<ag, 256, 196608>>>(out);
}